// round 1
// baseline (speedup 1.0000x reference)
#include <cuda_runtime.h>
#include <cmath>

#define T_ 4
#define B_ 8
#define C_ 512
#define N_ 1024
#define TB 32
#define CN (C_*N_)          // 524288
#define TBCN (TB*CN)        // 16777216 floats per full [T,B,C,N] tensor
#define PER_T (B_*CN)       // 4194304

// Scratch (static device globals — no runtime allocation)
__device__ float g_q[TBCN];
__device__ float g_k[TBCN];
__device__ float g_v[TBCN];
__device__ float g_a[TBCN];
__device__ float g_p[TBCN];
__device__ float g_kv[T_*B_*8*64*64];   // 1,048,576

// ============================================================================
// SGEMM (128x128x8 tile, 256 thr, 8x8 micro) + BatchNorm epilogue.
// Y[z] = BN( W @ X[z] (+ bias) )   for z in 0..31 (t*B+b slices)
// W: [512,512] row-major (o,c).  X,Y: [32][512][1024].
// BN matches jax op order: ((gamma * (y+bias)) * inv) + beta, no fma fusion.
// ============================================================================
__global__ __launch_bounds__(256) void sgemm_bn(
    const float* __restrict__ W, const float* __restrict__ X, float* __restrict__ Y,
    const float* __restrict__ gamma, const float* __restrict__ beta,
    const float* __restrict__ bias, float inv)
{
    __shared__ float As[8][128];   // A transposed: As[k][m]
    __shared__ float Bs[8][128];   // Bs[k][n]

    const int tid = threadIdx.x;
    const int m0 = blockIdx.y * 128;
    const int n0 = blockIdx.x * 128;
    const float* Xb = X + (size_t)blockIdx.z * CN;
    float*       Yb = Y + (size_t)blockIdx.z * CN;

    const int aRow = tid >> 1;          // 0..127
    const int aCol = (tid & 1) * 4;     // 0 or 4
    const int bRow = tid >> 5;          // 0..7
    const int bCol = (tid & 31) * 4;    // 0..124
    const int tx = tid & 15, ty = tid >> 4;

    float acc[8][8];
#pragma unroll
    for (int i = 0; i < 8; i++)
#pragma unroll
        for (int j = 0; j < 8; j++) acc[i][j] = 0.0f;

    for (int k0 = 0; k0 < C_; k0 += 8) {
        float4 av = *(const float4*)(W  + (size_t)(m0 + aRow) * C_ + k0 + aCol);
        float4 bv = *(const float4*)(Xb + (size_t)(k0 + bRow) * N_ + n0 + bCol);
        As[aCol + 0][aRow] = av.x;
        As[aCol + 1][aRow] = av.y;
        As[aCol + 2][aRow] = av.z;
        As[aCol + 3][aRow] = av.w;
        *(float4*)&Bs[bRow][bCol] = bv;
        __syncthreads();

#pragma unroll
        for (int k = 0; k < 8; k++) {
            float4 a0 = *(const float4*)&As[k][ty * 8];
            float4 a1 = *(const float4*)&As[k][ty * 8 + 4];
            float4 b0 = *(const float4*)&Bs[k][tx * 8];
            float4 b1 = *(const float4*)&Bs[k][tx * 8 + 4];
            float a_[8] = {a0.x, a0.y, a0.z, a0.w, a1.x, a1.y, a1.z, a1.w};
            float b_[8] = {b0.x, b0.y, b0.z, b0.w, b1.x, b1.y, b1.z, b1.w};
#pragma unroll
            for (int i = 0; i < 8; i++)
#pragma unroll
                for (int j = 0; j < 8; j++)
                    acc[i][j] += a_[i] * b_[j];
        }
        __syncthreads();
    }

#pragma unroll
    for (int i = 0; i < 8; i++) {
        int m = m0 + ty * 8 + i;
        float g = gamma[m];
        float be = beta[m];
        float bi = bias ? bias[m] : 0.0f;
#pragma unroll
        for (int j = 0; j < 8; j++) {
            float v = acc[i][j];
            if (bias) v = __fadd_rn(v, bi);
            v = __fmul_rn(g, v);
            v = __fmul_rn(v, inv);
            v = __fadd_rn(v, be);
            Yb[(size_t)m * N_ + n0 + tx * 8 + j] = v;
        }
    }
}

// ============================================================================
// Multi-step LIF: v' = v + (x - v)/2 ; s = (v' >= thr); hard reset.
// Exact op order (no fma contraction) to match the reference scan.
// ============================================================================
__global__ void lif_kernel(const float* __restrict__ in, float* __restrict__ out, float thr)
{
    size_t idx = (size_t)blockIdx.x * blockDim.x + threadIdx.x;
    if (idx >= PER_T) return;
    float v = 0.0f;
#pragma unroll
    for (int t = 0; t < T_; t++) {
        float x = in[(size_t)t * PER_T + idx];
        v = __fadd_rn(v, __fmul_rn(__fsub_rn(x, v), 0.5f));
        float s = (v >= thr) ? 1.0f : 0.0f;
        if (v >= thr) v = 0.0f;
        out[(size_t)t * PER_T + idx] = s;
    }
}

// ============================================================================
// kv[t,b,h,d1,d2] = sum_n Sk[t,b,h*64+d1,n] * Sv[t,b,h*64+d2,n]
// One block per (t,b,h): 64x64 output, K=1024. Integer-exact in fp32.
// ============================================================================
__global__ __launch_bounds__(256) void kv_kernel()
{
    int tbh = blockIdx.x;            // 0..255
    int tb = tbh >> 3, h = tbh & 7;
    const float* K = g_k + (size_t)tb * CN + (size_t)h * 64 * N_;
    const float* V = g_v + (size_t)tb * CN + (size_t)h * 64 * N_;

    __shared__ float Ks[64][65];     // [n][d] layout
    __shared__ float Vs[64][65];

    const int tid = threadIdx.x;
    const int tx = tid & 15, ty = tid >> 4;
    const int r = tid >> 2;           // d-row to load (0..63)
    const int c0 = (tid & 3) * 4;     // n-col group

    float acc[4][4];
#pragma unroll
    for (int i = 0; i < 4; i++)
#pragma unroll
        for (int j = 0; j < 4; j++) acc[i][j] = 0.0f;

    for (int nc = 0; nc < 16; nc++) {
        int nbase = nc * 64;
        __syncthreads();
#pragma unroll
        for (int c4 = 0; c4 < 4; c4++) {
            int nn = c0 + c4 * 16;
            float4 k4 = *(const float4*)(K + (size_t)r * N_ + nbase + nn);
            float4 v4 = *(const float4*)(V + (size_t)r * N_ + nbase + nn);
            Ks[nn + 0][r] = k4.x; Ks[nn + 1][r] = k4.y;
            Ks[nn + 2][r] = k4.z; Ks[nn + 3][r] = k4.w;
            Vs[nn + 0][r] = v4.x; Vs[nn + 1][r] = v4.y;
            Vs[nn + 2][r] = v4.z; Vs[nn + 3][r] = v4.w;
        }
        __syncthreads();
#pragma unroll 8
        for (int nn = 0; nn < 64; nn++) {
            float a_[4], b_[4];
#pragma unroll
            for (int i = 0; i < 4; i++) a_[i] = Ks[nn][ty * 4 + i];
#pragma unroll
            for (int j = 0; j < 4; j++) b_[j] = Vs[nn][tx * 4 + j];
#pragma unroll
            for (int i = 0; i < 4; i++)
#pragma unroll
                for (int j = 0; j < 4; j++)
                    acc[i][j] += a_[i] * b_[j];
        }
    }

    float* kvb = g_kv + (size_t)tbh * 4096;
#pragma unroll
    for (int i = 0; i < 4; i++)
#pragma unroll
        for (int j = 0; j < 4; j++)
            kvb[(ty * 4 + i) * 64 + (tx * 4 + j)] = acc[i][j];
}

// ============================================================================
// a[t,b,h*64+e,n] = 0.125 * sum_d Sq[t,b,h*64+d,n] * kv[t,b,h,d,e]
// Block = (tbh, n-tile of 128). Integer-exact * exact 0.125.
// ============================================================================
__global__ __launch_bounds__(256) void av_kernel()
{
    int tbh = blockIdx.y;
    int tb = tbh >> 3, h = tbh & 7;
    int n0 = blockIdx.x * 128;
    const float* Q  = g_q  + (size_t)tb * CN + (size_t)h * 64 * N_;
    const float* KV = g_kv + (size_t)tbh * 4096;
    float*       A  = g_a  + (size_t)tb * CN + (size_t)h * 64 * N_;

    __shared__ float Qs[64][128];    // [d][n]
    __shared__ float KVs[64][64];    // [d][e]

    const int tid = threadIdx.x;
#pragma unroll
    for (int i = 0; i < 4; i++) {
        int idx = tid + i * 256;               // 0..1023 float4s
        int r = idx >> 4, c = (idx & 15) * 4;
        *(float4*)&KVs[r][c] = *(const float4*)(KV + (size_t)r * 64 + c);
    }
#pragma unroll
    for (int i = 0; i < 8; i++) {
        int idx = tid + i * 256;               // 0..2047 float4s
        int r = idx >> 5, c = (idx & 31) * 4;
        *(float4*)&Qs[r][c] = *(const float4*)(Q + (size_t)r * N_ + n0 + c);
    }
    __syncthreads();

    const int tx = tid & 31, ty = tid >> 5;    // tx: n group of 4, ty: e group of 8
    float acc[8][4];
#pragma unroll
    for (int i = 0; i < 8; i++)
#pragma unroll
        for (int j = 0; j < 4; j++) acc[i][j] = 0.0f;

#pragma unroll 8
    for (int d = 0; d < 64; d++) {
        float4 q4 = *(const float4*)&Qs[d][tx * 4];
#pragma unroll
        for (int i = 0; i < 8; i++) {
            float kvv = KVs[d][ty * 8 + i];
            acc[i][0] += kvv * q4.x;
            acc[i][1] += kvv * q4.y;
            acc[i][2] += kvv * q4.z;
            acc[i][3] += kvv * q4.w;
        }
    }

#pragma unroll
    for (int i = 0; i < 8; i++) {
        int e = ty * 8 + i;
#pragma unroll
        for (int j = 0; j < 4; j++)
            A[(size_t)e * N_ + n0 + tx * 4 + j] = acc[i][j] * 0.125f;
    }
}

// ============================================================================
extern "C" void kernel_launch(void* const* d_in, const int* in_sizes, int n_in,
                              void* d_out, int out_size)
{
    const float* x   = (const float*)d_in[0];
    const float* Wq  = (const float*)d_in[1];
    const float* qg  = (const float*)d_in[2];
    const float* qb  = (const float*)d_in[3];
    const float* Wk  = (const float*)d_in[4];
    const float* kg  = (const float*)d_in[5];
    const float* kb  = (const float*)d_in[6];
    const float* Wv  = (const float*)d_in[7];
    const float* vg  = (const float*)d_in[8];
    const float* vb  = (const float*)d_in[9];
    const float* Wp  = (const float*)d_in[10];
    const float* bp  = (const float*)d_in[11];
    const float* pg  = (const float*)d_in[12];
    const float* pb  = (const float*)d_in[13];
    float* out = (float*)d_out;

    float *q, *k, *v, *a, *p;
    cudaGetSymbolAddress((void**)&q, g_q);
    cudaGetSymbolAddress((void**)&k, g_k);
    cudaGetSymbolAddress((void**)&v, g_v);
    cudaGetSymbolAddress((void**)&a, g_a);
    cudaGetSymbolAddress((void**)&p, g_p);

    float one_eps = 1.0f + 1e-5f;
    float inv = (float)(1.0 / sqrt((double)one_eps));

    dim3 gg(N_ / 128, C_ / 128, TB);

    sgemm_bn<<<gg, 256>>>(Wq, x, q, qg, qb, nullptr, inv);
    sgemm_bn<<<gg, 256>>>(Wk, x, k, kg, kb, nullptr, inv);
    sgemm_bn<<<gg, 256>>>(Wv, x, v, vg, vb, nullptr, inv);

    lif_kernel<<<PER_T / 256, 256>>>(q, q, 1.0f);
    lif_kernel<<<PER_T / 256, 256>>>(k, k, 1.0f);
    lif_kernel<<<PER_T / 256, 256>>>(v, v, 1.0f);

    kv_kernel<<<256, 256>>>();
    av_kernel<<<dim3(N_ / 128, 256), 256>>>();

    lif_kernel<<<PER_T / 256, 256>>>(a, a, 0.5f);

    sgemm_bn<<<gg, 256>>>(Wp, a, p, pg, pb, bp, inv);

    lif_kernel<<<PER_T / 256, 256>>>(p, out, 1.0f);
}

// round 3
// speedup vs baseline: 1.1680x; 1.1680x over previous
#include <cuda_runtime.h>
#include <cmath>
#include <cstdint>

#define T_ 4
#define B_ 8
#define C_ 512
#define N_ 1024
#define TB 32
#define CN (C_*N_)          // 524288
#define TBCN (TB*CN)        // 16777216
#define PER_T (B_*CN)       // 4194304

// Scratch (static device globals — no runtime allocation)
__device__ float g_q[TBCN];
__device__ float g_k[TBCN];
__device__ float g_v[TBCN];
__device__ float g_a[TBCN];          // attention pre-LIF / spikes [t][b][c][n]
__device__ float g_p[TBCN];          // projection pre-LIF
__device__ float g_kv[TB*8*64*64];

// ============================================================================
// helpers
// ============================================================================
__device__ __forceinline__ uint32_t f2tf(float v) {
    uint32_t r; asm("cvt.rna.tf32.f32 %0, %1;" : "=r"(r) : "f"(v)); return r;
}
__device__ __forceinline__ void mma8(float* c, const uint32_t* a, const uint32_t* b) {
    asm volatile("mma.sync.aligned.m16n8k8.row.col.f32.tf32.tf32.f32 "
                 "{%0,%1,%2,%3}, {%4,%5,%6,%7}, {%8,%9}, {%0,%1,%2,%3};"
                 : "+f"(c[0]), "+f"(c[1]), "+f"(c[2]), "+f"(c[3])
                 : "r"(a[0]), "r"(a[1]), "r"(a[2]), "r"(a[3]), "r"(b[0]), "r"(b[1]));
}

// ============================================================================
// tf32-split tensor-core GEMM + BatchNorm epilogue.
// Y[z][o][n] = BN( sum_c W[o][c] * X[z][c][n] (+bias) )
// A = W [m][k] row-major, B = X [k][n] (consumed directly, no transpose).
// CTA 128x128, 8 warps of 64x32, K-chunk 16, double-buffered, XOR-swizzled smem.
// NSPLIT=4: (Whi+Wlo)x(Xhi+Xlo) all terms.  NSPLIT=2 (binary B): (Whi+Wlo)xB.
// ============================================================================
template<int NSPLIT>
__global__ __launch_bounds__(256) void gemm_mma(
    const float* __restrict__ W, const float* __restrict__ X, float* __restrict__ Y,
    const float* __restrict__ gamma, const float* __restrict__ beta,
    const float* __restrict__ bias, float inv)
{
    extern __shared__ float sm[];
    float* sAh = sm;            // [2][16][128]
    float* sAl = sm + 4096;
    float* sBh = sm + 8192;
    float* sBl = sm + 12288;    // unused when NSPLIT==2

    const int tid  = threadIdx.x;
    const int lane = tid & 31;
    const int wid  = tid >> 5;
    const int wm   = (wid >> 2) * 64;   // warp m offset within CTA
    const int wn   = (wid & 3) * 32;    // warp n offset within CTA
    const int z  = blockIdx.z;
    const int m0 = blockIdx.y * 128;
    const int n0 = blockIdx.x * 128;

    const float* Xz = X + (size_t)z * CN;

    // loader indices: A: thread owns row m0+mA, k-range jA..jA+7 of each chunk
    const int mA = tid & 127;
    const int jA = (tid >> 7) * 8;
    // B: thread owns (k = kB, kB+8 ; n = nB..nB+3) of each 16x128 chunk
    const int kB = tid >> 5;            // 0..7
    const int nB = (tid & 31) * 4;

    const float* Wrow = W + (size_t)(m0 + mA) * C_ + jA;

    float acc[4][4][4];
#pragma unroll
    for (int i = 0; i < 4; i++)
#pragma unroll
        for (int j = 0; j < 4; j++)
#pragma unroll
            for (int e = 0; e < 4; e++) acc[i][j][e] = 0.0f;

    float4 wa0, wa1, xb0, xb1;

    auto LDG = [&](int ch) {
        const int kb = ch * 16;
        wa0 = *(const float4*)(Wrow + kb);
        wa1 = *(const float4*)(Wrow + kb + 4);
        xb0 = *(const float4*)(Xz + (size_t)(kb + kB) * N_ + n0 + nB);
        xb1 = *(const float4*)(Xz + (size_t)(kb + 8 + kB) * N_ + n0 + nB);
    };

    auto STS = [&](int st) {
        float* Ah = sAh + st * 2048;
        float* Al = sAl + st * 2048;
        float* Bh = sBh + st * 2048;
        float* Bl = sBl + st * 2048;
        float wv[8] = {wa0.x, wa0.y, wa0.z, wa0.w, wa1.x, wa1.y, wa1.z, wa1.w};
#pragma unroll
        for (int e = 0; e < 8; e++) {
            int k = jA + e;
            int idx = k * 128 + (mA ^ (8 * (k & 3)));
            uint32_t hi = f2tf(wv[e]);
            Ah[idx] = __uint_as_float(hi);
            Al[idx] = __uint_as_float(f2tf(wv[e] - __uint_as_float(hi)));
        }
        {
            int k = kB;
            int nsw = nB ^ (8 * (k & 3));
            if (NSPLIT == 4) {
                uint32_t hx = f2tf(xb0.x), hy = f2tf(xb0.y), hz = f2tf(xb0.z), hw = f2tf(xb0.w);
                float4 h = make_float4(__uint_as_float(hx), __uint_as_float(hy),
                                       __uint_as_float(hz), __uint_as_float(hw));
                float4 l = make_float4(
                    __uint_as_float(f2tf(xb0.x - h.x)), __uint_as_float(f2tf(xb0.y - h.y)),
                    __uint_as_float(f2tf(xb0.z - h.z)), __uint_as_float(f2tf(xb0.w - h.w)));
                *(float4*)(Bh + k * 128 + nsw) = h;
                *(float4*)(Bl + k * 128 + nsw) = l;
            } else {
                *(float4*)(Bh + k * 128 + nsw) = xb0;   // binary: exact tf32 already
            }
            k = kB + 8;
            nsw = nB ^ (8 * (k & 3));
            if (NSPLIT == 4) {
                uint32_t hx = f2tf(xb1.x), hy = f2tf(xb1.y), hz = f2tf(xb1.z), hw = f2tf(xb1.w);
                float4 h = make_float4(__uint_as_float(hx), __uint_as_float(hy),
                                       __uint_as_float(hz), __uint_as_float(hw));
                float4 l = make_float4(
                    __uint_as_float(f2tf(xb1.x - h.x)), __uint_as_float(f2tf(xb1.y - h.y)),
                    __uint_as_float(f2tf(xb1.z - h.z)), __uint_as_float(f2tf(xb1.w - h.w)));
                *(float4*)(Bh + k * 128 + nsw) = h;
                *(float4*)(Bl + k * 128 + nsw) = l;
            } else {
                *(float4*)(Bh + k * 128 + nsw) = xb1;
            }
        }
    };

    auto COMP = [&](int st) {
        const float* Ah = sAh + st * 2048;
        const float* Al = sAl + st * 2048;
        const float* Bh = sBh + st * 2048;
        const float* Bl = sBl + st * 2048;
        const int x8 = 8 * (lane & 3);
        const int q  = lane >> 2;
#pragma unroll
        for (int ks = 0; ks < 2; ks++) {
            const int k0 = ks * 8 + (lane & 3);
            uint32_t ah[4][4], al[4][4];
#pragma unroll
            for (int mt = 0; mt < 4; mt++) {
                int m  = wm + mt * 16 + q;
                int i0 = m ^ x8;
                int i1 = (m + 8) ^ x8;
                ah[mt][0] = __float_as_uint(Ah[k0 * 128 + i0]);
                ah[mt][1] = __float_as_uint(Ah[k0 * 128 + i1]);
                ah[mt][2] = __float_as_uint(Ah[(k0 + 4) * 128 + i0]);
                ah[mt][3] = __float_as_uint(Ah[(k0 + 4) * 128 + i1]);
                al[mt][0] = __float_as_uint(Al[k0 * 128 + i0]);
                al[mt][1] = __float_as_uint(Al[k0 * 128 + i1]);
                al[mt][2] = __float_as_uint(Al[(k0 + 4) * 128 + i0]);
                al[mt][3] = __float_as_uint(Al[(k0 + 4) * 128 + i1]);
            }
            uint32_t bb[4][2];
#pragma unroll
            for (int nt = 0; nt < 4; nt++) {
                int ib = (wn + nt * 8 + q) ^ x8;
                bb[nt][0] = __float_as_uint(Bh[k0 * 128 + ib]);
                bb[nt][1] = __float_as_uint(Bh[(k0 + 4) * 128 + ib]);
            }
#pragma unroll
            for (int mt = 0; mt < 4; mt++)
#pragma unroll
                for (int nt = 0; nt < 4; nt++) mma8(acc[mt][nt], ah[mt], bb[nt]);
#pragma unroll
            for (int mt = 0; mt < 4; mt++)
#pragma unroll
                for (int nt = 0; nt < 4; nt++) mma8(acc[mt][nt], al[mt], bb[nt]);
            if (NSPLIT == 4) {
#pragma unroll
                for (int nt = 0; nt < 4; nt++) {
                    int ib = (wn + nt * 8 + q) ^ x8;
                    bb[nt][0] = __float_as_uint(Bl[k0 * 128 + ib]);
                    bb[nt][1] = __float_as_uint(Bl[(k0 + 4) * 128 + ib]);
                }
#pragma unroll
                for (int mt = 0; mt < 4; mt++)
#pragma unroll
                    for (int nt = 0; nt < 4; nt++) mma8(acc[mt][nt], ah[mt], bb[nt]);
#pragma unroll
                for (int mt = 0; mt < 4; mt++)
#pragma unroll
                    for (int nt = 0; nt < 4; nt++) mma8(acc[mt][nt], al[mt], bb[nt]);
            }
        }
    };

    LDG(0);
    STS(0);
    __syncthreads();
#pragma unroll 1
    for (int ch = 0; ch < 32; ch++) {
        if (ch < 31) LDG(ch + 1);
        COMP(ch & 1);
        if (ch < 31) STS((ch + 1) & 1);
        __syncthreads();
    }

    // Epilogue: BN in exact jax op order, float2 stores.
    {
        const int rb = m0 + wm + (lane >> 2);
        const int cb = n0 + wn + 2 * (lane & 3);
        float* Yz = Y + (size_t)z * CN;
#pragma unroll
        for (int mt = 0; mt < 4; mt++) {
            int r0 = rb + mt * 16, r1 = r0 + 8;
            float g0 = gamma[r0], g1 = gamma[r1];
            float e0 = beta[r0],  e1 = beta[r1];
            float b0 = bias ? bias[r0] : 0.0f;
            float b1 = bias ? bias[r1] : 0.0f;
#pragma unroll
            for (int nt = 0; nt < 4; nt++) {
                int cc = cb + nt * 8;
                float* c = acc[mt][nt];
                float v0 = c[0], v1 = c[1], v2 = c[2], v3 = c[3];
                if (bias) { v0 = __fadd_rn(v0, b0); v1 = __fadd_rn(v1, b0);
                            v2 = __fadd_rn(v2, b1); v3 = __fadd_rn(v3, b1); }
                v0 = __fadd_rn(__fmul_rn(__fmul_rn(g0, v0), inv), e0);
                v1 = __fadd_rn(__fmul_rn(__fmul_rn(g0, v1), inv), e0);
                v2 = __fadd_rn(__fmul_rn(__fmul_rn(g1, v2), inv), e1);
                v3 = __fadd_rn(__fmul_rn(__fmul_rn(g1, v3), inv), e1);
                *(float2*)(Yz + (size_t)r0 * N_ + cc) = make_float2(v0, v1);
                *(float2*)(Yz + (size_t)r1 * N_ + cc) = make_float2(v2, v3);
            }
        }
    }
}

// ============================================================================
// Multi-step LIF: v' = v + (x - v)/2 ; s = (v' >= thr); hard reset.
// ============================================================================
__global__ void lif_kernel(const float* __restrict__ in, float* __restrict__ out, float thr)
{
    size_t idx = (size_t)blockIdx.x * blockDim.x + threadIdx.x;
    if (idx >= PER_T) return;
    float v = 0.0f;
#pragma unroll
    for (int t = 0; t < T_; t++) {
        float x = in[(size_t)t * PER_T + idx];
        v = __fadd_rn(v, __fmul_rn(__fsub_rn(x, v), 0.5f));
        float s = (v >= thr) ? 1.0f : 0.0f;
        if (v >= thr) v = 0.0f;
        out[(size_t)t * PER_T + idx] = s;
    }
}

// ============================================================================
// kv[t,b,h,d1,d2] = sum_n Sk[.,d1,n]*Sv[.,d2,n]   (integer-exact)
// ============================================================================
__global__ __launch_bounds__(256) void kv_kernel()
{
    int tbh = blockIdx.x;
    int tb = tbh >> 3, h = tbh & 7;
    const float* K = g_k + (size_t)tb * CN + (size_t)h * 64 * N_;
    const float* V = g_v + (size_t)tb * CN + (size_t)h * 64 * N_;

    __shared__ float Ks[64][65];
    __shared__ float Vs[64][65];

    const int tid = threadIdx.x;
    const int tx = tid & 15, ty = tid >> 4;
    const int r = tid >> 2;
    const int c0 = (tid & 3) * 4;

    float acc[4][4];
#pragma unroll
    for (int i = 0; i < 4; i++)
#pragma unroll
        for (int j = 0; j < 4; j++) acc[i][j] = 0.0f;

    for (int nc = 0; nc < 16; nc++) {
        int nbase = nc * 64;
        __syncthreads();
#pragma unroll
        for (int c4 = 0; c4 < 4; c4++) {
            int nn = c0 + c4 * 16;
            float4 k4 = *(const float4*)(K + (size_t)r * N_ + nbase + nn);
            float4 v4 = *(const float4*)(V + (size_t)r * N_ + nbase + nn);
            Ks[nn + 0][r] = k4.x; Ks[nn + 1][r] = k4.y;
            Ks[nn + 2][r] = k4.z; Ks[nn + 3][r] = k4.w;
            Vs[nn + 0][r] = v4.x; Vs[nn + 1][r] = v4.y;
            Vs[nn + 2][r] = v4.z; Vs[nn + 3][r] = v4.w;
        }
        __syncthreads();
#pragma unroll 8
        for (int nn = 0; nn < 64; nn++) {
            float a_[4], b_[4];
#pragma unroll
            for (int i = 0; i < 4; i++) a_[i] = Ks[nn][ty * 4 + i];
#pragma unroll
            for (int j = 0; j < 4; j++) b_[j] = Vs[nn][tx * 4 + j];
#pragma unroll
            for (int i = 0; i < 4; i++)
#pragma unroll
                for (int j = 0; j < 4; j++)
                    acc[i][j] += a_[i] * b_[j];
        }
    }

    float* kvb = g_kv + (size_t)tbh * 4096;
#pragma unroll
    for (int i = 0; i < 4; i++)
#pragma unroll
        for (int j = 0; j < 4; j++)
            kvb[(ty * 4 + i) * 64 + (tx * 4 + j)] = acc[i][j];
}

// ============================================================================
// a[t,b,h*64+e,n] = 0.125 * sum_d Sq[.,d,n] * kv[.,d,e]   (integer-exact)
// ============================================================================
__global__ __launch_bounds__(256) void av_kernel()
{
    int tbh = blockIdx.y;
    int tb = tbh >> 3, h = tbh & 7;
    int n0 = blockIdx.x * 128;
    const float* Q  = g_q  + (size_t)tb * CN + (size_t)h * 64 * N_;
    const float* KV = g_kv + (size_t)tbh * 4096;
    float*       A  = g_a  + (size_t)tb * CN + (size_t)h * 64 * N_;

    __shared__ float Qs[64][128];
    __shared__ float KVs[64][64];

    const int tid = threadIdx.x;
#pragma unroll
    for (int i = 0; i < 4; i++) {
        int idx = tid + i * 256;
        int r = idx >> 4, c = (idx & 15) * 4;
        *(float4*)&KVs[r][c] = *(const float4*)(KV + (size_t)r * 64 + c);
    }
#pragma unroll
    for (int i = 0; i < 8; i++) {
        int idx = tid + i * 256;
        int r = idx >> 5, c = (idx & 31) * 4;
        *(float4*)&Qs[r][c] = *(const float4*)(Q + (size_t)r * N_ + n0 + c);
    }
    __syncthreads();

    const int tx = tid & 31, ty = tid >> 5;
    float acc[8][4];
#pragma unroll
    for (int i = 0; i < 8; i++)
#pragma unroll
        for (int j = 0; j < 4; j++) acc[i][j] = 0.0f;

#pragma unroll 8
    for (int d = 0; d < 64; d++) {
        float4 q4 = *(const float4*)&Qs[d][tx * 4];
#pragma unroll
        for (int i = 0; i < 8; i++) {
            float kvv = KVs[d][ty * 8 + i];
            acc[i][0] += kvv * q4.x;
            acc[i][1] += kvv * q4.y;
            acc[i][2] += kvv * q4.z;
            acc[i][3] += kvv * q4.w;
        }
    }

#pragma unroll
    for (int i = 0; i < 8; i++) {
        int e = ty * 8 + i;
#pragma unroll
        for (int j = 0; j < 4; j++)
            A[(size_t)e * N_ + n0 + tx * 4 + j] = acc[i][j] * 0.125f;
    }
}

// ============================================================================
extern "C" void kernel_launch(void* const* d_in, const int* in_sizes, int n_in,
                              void* d_out, int out_size)
{
    const float* x   = (const float*)d_in[0];
    const float* Wq  = (const float*)d_in[1];
    const float* qg  = (const float*)d_in[2];
    const float* qb  = (const float*)d_in[3];
    const float* Wk  = (const float*)d_in[4];
    const float* kg  = (const float*)d_in[5];
    const float* kb  = (const float*)d_in[6];
    const float* Wv  = (const float*)d_in[7];
    const float* vg  = (const float*)d_in[8];
    const float* vb  = (const float*)d_in[9];
    const float* Wp  = (const float*)d_in[10];
    const float* bp  = (const float*)d_in[11];
    const float* pg  = (const float*)d_in[12];
    const float* pb  = (const float*)d_in[13];
    float* out = (float*)d_out;

    float *q, *k, *v, *a, *p;
    cudaGetSymbolAddress((void**)&q, g_q);
    cudaGetSymbolAddress((void**)&k, g_k);
    cudaGetSymbolAddress((void**)&v, g_v);
    cudaGetSymbolAddress((void**)&a, g_a);
    cudaGetSymbolAddress((void**)&p, g_p);

    float one_eps = 1.0f + 1e-5f;
    float inv = (float)(1.0 / sqrt((double)one_eps));

    const int SMEM_BYTES = 65536;
    cudaFuncSetAttribute(gemm_mma<4>, cudaFuncAttributeMaxDynamicSharedMemorySize, SMEM_BYTES);
    cudaFuncSetAttribute(gemm_mma<2>, cudaFuncAttributeMaxDynamicSharedMemorySize, SMEM_BYTES);

    dim3 gg(N_ / 128, C_ / 128, TB);   // 8 x 4 x 32

    gemm_mma<4><<<gg, 256, SMEM_BYTES>>>(Wq, x, q, qg, qb, nullptr, inv);
    gemm_mma<4><<<gg, 256, SMEM_BYTES>>>(Wk, x, k, kg, kb, nullptr, inv);
    gemm_mma<4><<<gg, 256, SMEM_BYTES>>>(Wv, x, v, vg, vb, nullptr, inv);

    lif_kernel<<<PER_T / 256, 256>>>(q, q, 1.0f);
    lif_kernel<<<PER_T / 256, 256>>>(k, k, 1.0f);
    lif_kernel<<<PER_T / 256, 256>>>(v, v, 1.0f);

    kv_kernel<<<256, 256>>>();
    av_kernel<<<dim3(N_ / 128, 256), 256>>>();

    lif_kernel<<<PER_T / 256, 256>>>(a, a, 0.5f);

    gemm_mma<2><<<gg, 256, SMEM_BYTES>>>(Wp, a, p, pg, pb, bp, inv);

    lif_kernel<<<PER_T / 256, 256>>>(p, out, 1.0f);
}

// round 4
// speedup vs baseline: 1.3199x; 1.1300x over previous
#include <cuda_runtime.h>
#include <cmath>
#include <cstdint>

#define T_ 4
#define B_ 8
#define C_ 512
#define N_ 1024
#define TB 32
#define CN (C_*N_)          // 524288
#define TBCN (TB*CN)        // 16777216
#define PER_T (B_*CN)       // 4194304

// Scratch (static device globals — no runtime allocation)
__device__ float g_q[TBCN];
__device__ float g_k[TBCN];
__device__ float g_v[TBCN];
__device__ float g_a[TBCN];          // attention pre-LIF / spikes [t][b][c][n]
__device__ float g_p[TBCN];          // projection pre-LIF
__device__ float g_kv[TB*8*64*64];

// ============================================================================
// helpers
// ============================================================================
__device__ __forceinline__ uint32_t f2tf(float v) {
    uint32_t r; asm("cvt.rna.tf32.f32 %0, %1;" : "=r"(r) : "f"(v)); return r;
}
__device__ __forceinline__ void mma8(float* c, const uint32_t* a, const uint32_t* b) {
    asm volatile("mma.sync.aligned.m16n8k8.row.col.f32.tf32.tf32.f32 "
                 "{%0,%1,%2,%3}, {%4,%5,%6,%7}, {%8,%9}, {%0,%1,%2,%3};"
                 : "+f"(c[0]), "+f"(c[1]), "+f"(c[2]), "+f"(c[3])
                 : "r"(a[0]), "r"(a[1]), "r"(a[2]), "r"(a[3]), "r"(b[0]), "r"(b[1]));
}

// ============================================================================
// tf32-split tensor-core GEMM + BatchNorm epilogue.
// Y[z][o][n] = BN( sum_c W[o][c] * X[z][c][n] (+bias) )
// A = W [m][k] row-major, B = X [k][n] (consumed directly, no transpose).
// CTA 128x128, 8 warps of 64x32, K-chunk 16, double-buffered, XOR-swizzled smem.
// NSPLIT=3 (3xTF32): hi*hi + lo*hi + hi*lo  (drops lo*lo, ~2^-22 rel)
// NSPLIT=2 (binary B, exact): hi*B + lo*B
// ============================================================================
template<int NSPLIT>
__global__ __launch_bounds__(256) void gemm_mma(
    const float* __restrict__ W, const float* __restrict__ X, float* __restrict__ Y,
    const float* __restrict__ gamma, const float* __restrict__ beta,
    const float* __restrict__ bias, float inv)
{
    extern __shared__ float sm[];
    float* sAh = sm;            // [2][16][128]
    float* sAl = sm + 4096;
    float* sBh = sm + 8192;
    float* sBl = sm + 12288;    // unused when NSPLIT==2

    const int tid  = threadIdx.x;
    const int lane = tid & 31;
    const int wid  = tid >> 5;
    const int wm   = (wid >> 2) * 64;   // warp m offset within CTA
    const int wn   = (wid & 3) * 32;    // warp n offset within CTA
    const int z  = blockIdx.z;
    const int m0 = blockIdx.y * 128;
    const int n0 = blockIdx.x * 128;

    const float* Xz = X + (size_t)z * CN;

    // loader indices: A: thread owns row m0+mA, k-range jA..jA+7 of each chunk
    const int mA = tid & 127;
    const int jA = (tid >> 7) * 8;
    // B: thread owns (k = kB, kB+8 ; n = nB..nB+3) of each 16x128 chunk
    const int kB = tid >> 5;            // 0..7
    const int nB = (tid & 31) * 4;

    const float* Wrow = W + (size_t)(m0 + mA) * C_ + jA;

    float acc[4][4][4];
#pragma unroll
    for (int i = 0; i < 4; i++)
#pragma unroll
        for (int j = 0; j < 4; j++)
#pragma unroll
            for (int e = 0; e < 4; e++) acc[i][j][e] = 0.0f;

    float4 wa0, wa1, xb0, xb1;

    auto LDG = [&](int ch) {
        const int kb = ch * 16;
        wa0 = *(const float4*)(Wrow + kb);
        wa1 = *(const float4*)(Wrow + kb + 4);
        xb0 = *(const float4*)(Xz + (size_t)(kb + kB) * N_ + n0 + nB);
        xb1 = *(const float4*)(Xz + (size_t)(kb + 8 + kB) * N_ + n0 + nB);
    };

    auto STS = [&](int st) {
        float* Ah = sAh + st * 2048;
        float* Al = sAl + st * 2048;
        float* Bh = sBh + st * 2048;
        float* Bl = sBl + st * 2048;
        float wv[8] = {wa0.x, wa0.y, wa0.z, wa0.w, wa1.x, wa1.y, wa1.z, wa1.w};
#pragma unroll
        for (int e = 0; e < 8; e++) {
            int k = jA + e;
            int idx = k * 128 + (mA ^ (8 * (k & 3)));
            uint32_t hi = f2tf(wv[e]);
            Ah[idx] = __uint_as_float(hi);
            Al[idx] = __uint_as_float(f2tf(wv[e] - __uint_as_float(hi)));
        }
        {
            int k = kB;
            int nsw = nB ^ (8 * (k & 3));
            if (NSPLIT >= 3) {
                uint32_t hx = f2tf(xb0.x), hy = f2tf(xb0.y), hz = f2tf(xb0.z), hw = f2tf(xb0.w);
                float4 h = make_float4(__uint_as_float(hx), __uint_as_float(hy),
                                       __uint_as_float(hz), __uint_as_float(hw));
                float4 l = make_float4(
                    __uint_as_float(f2tf(xb0.x - h.x)), __uint_as_float(f2tf(xb0.y - h.y)),
                    __uint_as_float(f2tf(xb0.z - h.z)), __uint_as_float(f2tf(xb0.w - h.w)));
                *(float4*)(Bh + k * 128 + nsw) = h;
                *(float4*)(Bl + k * 128 + nsw) = l;
            } else {
                *(float4*)(Bh + k * 128 + nsw) = xb0;   // binary: exact tf32 already
            }
            k = kB + 8;
            nsw = nB ^ (8 * (k & 3));
            if (NSPLIT >= 3) {
                uint32_t hx = f2tf(xb1.x), hy = f2tf(xb1.y), hz = f2tf(xb1.z), hw = f2tf(xb1.w);
                float4 h = make_float4(__uint_as_float(hx), __uint_as_float(hy),
                                       __uint_as_float(hz), __uint_as_float(hw));
                float4 l = make_float4(
                    __uint_as_float(f2tf(xb1.x - h.x)), __uint_as_float(f2tf(xb1.y - h.y)),
                    __uint_as_float(f2tf(xb1.z - h.z)), __uint_as_float(f2tf(xb1.w - h.w)));
                *(float4*)(Bh + k * 128 + nsw) = h;
                *(float4*)(Bl + k * 128 + nsw) = l;
            } else {
                *(float4*)(Bh + k * 128 + nsw) = xb1;
            }
        }
    };

    auto COMP = [&](int st) {
        const float* Ah = sAh + st * 2048;
        const float* Al = sAl + st * 2048;
        const float* Bh = sBh + st * 2048;
        const float* Bl = sBl + st * 2048;
        const int x8 = 8 * (lane & 3);
        const int q  = lane >> 2;
#pragma unroll
        for (int ks = 0; ks < 2; ks++) {
            const int k0 = ks * 8 + (lane & 3);
            uint32_t ah[4][4], al[4][4];
#pragma unroll
            for (int mt = 0; mt < 4; mt++) {
                int m  = wm + mt * 16 + q;
                int i0 = m ^ x8;
                int i1 = (m + 8) ^ x8;
                ah[mt][0] = __float_as_uint(Ah[k0 * 128 + i0]);
                ah[mt][1] = __float_as_uint(Ah[k0 * 128 + i1]);
                ah[mt][2] = __float_as_uint(Ah[(k0 + 4) * 128 + i0]);
                ah[mt][3] = __float_as_uint(Ah[(k0 + 4) * 128 + i1]);
                al[mt][0] = __float_as_uint(Al[k0 * 128 + i0]);
                al[mt][1] = __float_as_uint(Al[k0 * 128 + i1]);
                al[mt][2] = __float_as_uint(Al[(k0 + 4) * 128 + i0]);
                al[mt][3] = __float_as_uint(Al[(k0 + 4) * 128 + i1]);
            }
            uint32_t bh[4][2];
#pragma unroll
            for (int nt = 0; nt < 4; nt++) {
                int ib = (wn + nt * 8 + q) ^ x8;
                bh[nt][0] = __float_as_uint(Bh[k0 * 128 + ib]);
                bh[nt][1] = __float_as_uint(Bh[(k0 + 4) * 128 + ib]);
            }
            // term 1: Ahi x Bhi
#pragma unroll
            for (int mt = 0; mt < 4; mt++)
#pragma unroll
                for (int nt = 0; nt < 4; nt++) mma8(acc[mt][nt], ah[mt], bh[nt]);
            // term 2: Alo x Bhi
#pragma unroll
            for (int mt = 0; mt < 4; mt++)
#pragma unroll
                for (int nt = 0; nt < 4; nt++) mma8(acc[mt][nt], al[mt], bh[nt]);
            // term 3: Ahi x Blo  (3xTF32; skipped for binary B)
            if (NSPLIT >= 3) {
                uint32_t bl[4][2];
#pragma unroll
                for (int nt = 0; nt < 4; nt++) {
                    int ib = (wn + nt * 8 + q) ^ x8;
                    bl[nt][0] = __float_as_uint(Bl[k0 * 128 + ib]);
                    bl[nt][1] = __float_as_uint(Bl[(k0 + 4) * 128 + ib]);
                }
#pragma unroll
                for (int mt = 0; mt < 4; mt++)
#pragma unroll
                    for (int nt = 0; nt < 4; nt++) mma8(acc[mt][nt], ah[mt], bl[nt]);
            }
        }
    };

    LDG(0);
    STS(0);
    __syncthreads();
#pragma unroll 1
    for (int ch = 0; ch < 32; ch++) {
        if (ch < 31) LDG(ch + 1);
        COMP(ch & 1);
        if (ch < 31) STS((ch + 1) & 1);
        __syncthreads();
    }

    // Epilogue: BN in exact jax op order, float2 stores.
    {
        const int rb = m0 + wm + (lane >> 2);
        const int cb = n0 + wn + 2 * (lane & 3);
        float* Yz = Y + (size_t)z * CN;
#pragma unroll
        for (int mt = 0; mt < 4; mt++) {
            int r0 = rb + mt * 16, r1 = r0 + 8;
            float g0 = gamma[r0], g1 = gamma[r1];
            float e0 = beta[r0],  e1 = beta[r1];
            float b0 = bias ? bias[r0] : 0.0f;
            float b1 = bias ? bias[r1] : 0.0f;
#pragma unroll
            for (int nt = 0; nt < 4; nt++) {
                int cc = cb + nt * 8;
                float* c = acc[mt][nt];
                float v0 = c[0], v1 = c[1], v2 = c[2], v3 = c[3];
                if (bias) { v0 = __fadd_rn(v0, b0); v1 = __fadd_rn(v1, b0);
                            v2 = __fadd_rn(v2, b1); v3 = __fadd_rn(v3, b1); }
                v0 = __fadd_rn(__fmul_rn(__fmul_rn(g0, v0), inv), e0);
                v1 = __fadd_rn(__fmul_rn(__fmul_rn(g0, v1), inv), e0);
                v2 = __fadd_rn(__fmul_rn(__fmul_rn(g1, v2), inv), e1);
                v3 = __fadd_rn(__fmul_rn(__fmul_rn(g1, v3), inv), e1);
                *(float2*)(Yz + (size_t)r0 * N_ + cc) = make_float2(v0, v1);
                *(float2*)(Yz + (size_t)r1 * N_ + cc) = make_float2(v2, v3);
            }
        }
    }
}

// ============================================================================
// Multi-step LIF: v' = v + (x - v)/2 ; s = (v' >= thr); hard reset.
// ============================================================================
__global__ void lif_kernel(const float* __restrict__ in, float* __restrict__ out, float thr)
{
    size_t idx = (size_t)blockIdx.x * blockDim.x + threadIdx.x;
    if (idx >= PER_T) return;
    float v = 0.0f;
#pragma unroll
    for (int t = 0; t < T_; t++) {
        float x = in[(size_t)t * PER_T + idx];
        v = __fadd_rn(v, __fmul_rn(__fsub_rn(x, v), 0.5f));
        float s = (v >= thr) ? 1.0f : 0.0f;
        if (v >= thr) v = 0.0f;
        out[(size_t)t * PER_T + idx] = s;
    }
}

// ============================================================================
// kv[t,b,h,d1,d2] = sum_n Sk[.,d1,n]*Sv[.,d2,n]   (integer-exact)
// ============================================================================
__global__ __launch_bounds__(256) void kv_kernel()
{
    int tbh = blockIdx.x;
    int tb = tbh >> 3, h = tbh & 7;
    const float* K = g_k + (size_t)tb * CN + (size_t)h * 64 * N_;
    const float* V = g_v + (size_t)tb * CN + (size_t)h * 64 * N_;

    __shared__ float Ks[64][65];
    __shared__ float Vs[64][65];

    const int tid = threadIdx.x;
    const int tx = tid & 15, ty = tid >> 4;
    const int r = tid >> 2;
    const int c0 = (tid & 3) * 4;

    float acc[4][4];
#pragma unroll
    for (int i = 0; i < 4; i++)
#pragma unroll
        for (int j = 0; j < 4; j++) acc[i][j] = 0.0f;

    for (int nc = 0; nc < 16; nc++) {
        int nbase = nc * 64;
        __syncthreads();
#pragma unroll
        for (int c4 = 0; c4 < 4; c4++) {
            int nn = c0 + c4 * 16;
            float4 k4 = *(const float4*)(K + (size_t)r * N_ + nbase + nn);
            float4 v4 = *(const float4*)(V + (size_t)r * N_ + nbase + nn);
            Ks[nn + 0][r] = k4.x; Ks[nn + 1][r] = k4.y;
            Ks[nn + 2][r] = k4.z; Ks[nn + 3][r] = k4.w;
            Vs[nn + 0][r] = v4.x; Vs[nn + 1][r] = v4.y;
            Vs[nn + 2][r] = v4.z; Vs[nn + 3][r] = v4.w;
        }
        __syncthreads();
#pragma unroll 8
        for (int nn = 0; nn < 64; nn++) {
            float a_[4], b_[4];
#pragma unroll
            for (int i = 0; i < 4; i++) a_[i] = Ks[nn][ty * 4 + i];
#pragma unroll
            for (int j = 0; j < 4; j++) b_[j] = Vs[nn][tx * 4 + j];
#pragma unroll
            for (int i = 0; i < 4; i++)
#pragma unroll
                for (int j = 0; j < 4; j++)
                    acc[i][j] += a_[i] * b_[j];
        }
    }

    float* kvb = g_kv + (size_t)tbh * 4096;
#pragma unroll
    for (int i = 0; i < 4; i++)
#pragma unroll
        for (int j = 0; j < 4; j++)
            kvb[(ty * 4 + i) * 64 + (tx * 4 + j)] = acc[i][j];
}

// ============================================================================
// a[t,b,h*64+e,n] = 0.125 * sum_d Sq[.,d,n] * kv[.,d,e]   (integer-exact)
// ============================================================================
__global__ __launch_bounds__(256) void av_kernel()
{
    int tbh = blockIdx.y;
    int tb = tbh >> 3, h = tbh & 7;
    int n0 = blockIdx.x * 128;
    const float* Q  = g_q  + (size_t)tb * CN + (size_t)h * 64 * N_;
    const float* KV = g_kv + (size_t)tbh * 4096;
    float*       A  = g_a  + (size_t)tb * CN + (size_t)h * 64 * N_;

    __shared__ float Qs[64][128];
    __shared__ float KVs[64][64];

    const int tid = threadIdx.x;
#pragma unroll
    for (int i = 0; i < 4; i++) {
        int idx = tid + i * 256;
        int r = idx >> 4, c = (idx & 15) * 4;
        *(float4*)&KVs[r][c] = *(const float4*)(KV + (size_t)r * 64 + c);
    }
#pragma unroll
    for (int i = 0; i < 8; i++) {
        int idx = tid + i * 256;
        int r = idx >> 5, c = (idx & 31) * 4;
        *(float4*)&Qs[r][c] = *(const float4*)(Q + (size_t)r * N_ + n0 + c);
    }
    __syncthreads();

    const int tx = tid & 31, ty = tid >> 5;
    float acc[8][4];
#pragma unroll
    for (int i = 0; i < 8; i++)
#pragma unroll
        for (int j = 0; j < 4; j++) acc[i][j] = 0.0f;

#pragma unroll 8
    for (int d = 0; d < 64; d++) {
        float4 q4 = *(const float4*)&Qs[d][tx * 4];
#pragma unroll
        for (int i = 0; i < 8; i++) {
            float kvv = KVs[d][ty * 8 + i];
            acc[i][0] += kvv * q4.x;
            acc[i][1] += kvv * q4.y;
            acc[i][2] += kvv * q4.z;
            acc[i][3] += kvv * q4.w;
        }
    }

#pragma unroll
    for (int i = 0; i < 8; i++) {
        int e = ty * 8 + i;
#pragma unroll
        for (int j = 0; j < 4; j++)
            A[(size_t)e * N_ + n0 + tx * 4 + j] = acc[i][j] * 0.125f;
    }
}

// ============================================================================
extern "C" void kernel_launch(void* const* d_in, const int* in_sizes, int n_in,
                              void* d_out, int out_size)
{
    const float* x   = (const float*)d_in[0];
    const float* Wq  = (const float*)d_in[1];
    const float* qg  = (const float*)d_in[2];
    const float* qb  = (const float*)d_in[3];
    const float* Wk  = (const float*)d_in[4];
    const float* kg  = (const float*)d_in[5];
    const float* kb  = (const float*)d_in[6];
    const float* Wv  = (const float*)d_in[7];
    const float* vg  = (const float*)d_in[8];
    const float* vb  = (const float*)d_in[9];
    const float* Wp  = (const float*)d_in[10];
    const float* bp  = (const float*)d_in[11];
    const float* pg  = (const float*)d_in[12];
    const float* pb  = (const float*)d_in[13];
    float* out = (float*)d_out;

    float *q, *k, *v, *a, *p;
    cudaGetSymbolAddress((void**)&q, g_q);
    cudaGetSymbolAddress((void**)&k, g_k);
    cudaGetSymbolAddress((void**)&v, g_v);
    cudaGetSymbolAddress((void**)&a, g_a);
    cudaGetSymbolAddress((void**)&p, g_p);

    float one_eps = 1.0f + 1e-5f;
    float inv = (float)(1.0 / sqrt((double)one_eps));

    const int SMEM_BYTES = 65536;
    cudaFuncSetAttribute(gemm_mma<3>, cudaFuncAttributeMaxDynamicSharedMemorySize, SMEM_BYTES);
    cudaFuncSetAttribute(gemm_mma<2>, cudaFuncAttributeMaxDynamicSharedMemorySize, SMEM_BYTES);

    dim3 gg(N_ / 128, C_ / 128, TB);   // 8 x 4 x 32

    gemm_mma<3><<<gg, 256, SMEM_BYTES>>>(Wq, x, q, qg, qb, nullptr, inv);
    gemm_mma<3><<<gg, 256, SMEM_BYTES>>>(Wk, x, k, kg, kb, nullptr, inv);
    gemm_mma<3><<<gg, 256, SMEM_BYTES>>>(Wv, x, v, vg, vb, nullptr, inv);

    lif_kernel<<<PER_T / 256, 256>>>(q, q, 1.0f);
    lif_kernel<<<PER_T / 256, 256>>>(k, k, 1.0f);
    lif_kernel<<<PER_T / 256, 256>>>(v, v, 1.0f);

    kv_kernel<<<256, 256>>>();
    av_kernel<<<dim3(N_ / 128, 256), 256>>>();

    lif_kernel<<<PER_T / 256, 256>>>(a, a, 0.5f);

    gemm_mma<2><<<gg, 256, SMEM_BYTES>>>(Wp, a, p, pg, pb, bp, inv);

    lif_kernel<<<PER_T / 256, 256>>>(p, out, 1.0f);
}

// round 5
// speedup vs baseline: 2.4507x; 1.8567x over previous
#include <cuda_runtime.h>
#include <cuda_fp16.h>
#include <cmath>
#include <cstdint>

#define T_ 4
#define B_ 8
#define C_ 512
#define N_ 1024
#define TB 32
#define CN (C_*N_)          // 524288
#define TBCN (TB*CN)        // 16777216
#define PER_T (B_*CN)       // 4194304

// Scratch (static device globals — no runtime allocation)
__device__ float g_q[TBCN];
__device__ float g_k[TBCN];
__device__ float g_v[TBCN];
__device__ float g_a[TBCN];          // attention pre-LIF / spikes [t][b][c][n]
__device__ float g_p[TBCN];          // projection pre-LIF
__device__ float g_kv[TB*8*64*64];

#define WSCALE     2048.0f
#define WSCALE_INV 4.8828125e-4f     // 2^-11, exact

// ============================================================================
// helpers
// ============================================================================
__device__ __forceinline__ uint32_t smem_u32(const void* p) {
    uint32_t a;
    asm("{ .reg .u64 t; cvta.to.shared.u64 t, %1; cvt.u32.u64 %0, t; }" : "=r"(a) : "l"(p));
    return a;
}
__device__ __forceinline__ uint32_t packh(__half a, __half b) {
    __half2 h = __halves2half2(a, b);
    return *(uint32_t*)&h;
}
__device__ __forceinline__ void ldmx4(uint32_t* r, uint32_t addr) {
    asm volatile("ldmatrix.sync.aligned.m8n8.x4.shared.b16 {%0,%1,%2,%3}, [%4];"
                 : "=r"(r[0]), "=r"(r[1]), "=r"(r[2]), "=r"(r[3]) : "r"(addr));
}
__device__ __forceinline__ void ldmx4t(uint32_t* r, uint32_t addr) {
    asm volatile("ldmatrix.sync.aligned.m8n8.x4.trans.shared.b16 {%0,%1,%2,%3}, [%4];"
                 : "=r"(r[0]), "=r"(r[1]), "=r"(r[2]), "=r"(r[3]) : "r"(addr));
}
__device__ __forceinline__ void mma16(float* c, const uint32_t* a, const uint32_t* b) {
    asm volatile("mma.sync.aligned.m16n8k16.row.col.f32.f16.f16.f32 "
                 "{%0,%1,%2,%3}, {%4,%5,%6,%7}, {%8,%9}, {%0,%1,%2,%3};"
                 : "+f"(c[0]), "+f"(c[1]), "+f"(c[2]), "+f"(c[3])
                 : "r"(a[0]), "r"(a[1]), "r"(a[2]), "r"(a[3]), "r"(b[0]), "r"(b[1]));
}

// Panel layouts (bytes within a 4KB panel):
//   A(m, k):  h=k>>3;  byte = (m*2 + (h ^ ((m>>2)&1)))*16 + (k&7)*2
//   B(k, n):  g=n>>3;  byte = k*256 + ((g ^ (k&7)))*16 + (n&7)*2
// Both give conflict-free STS and ldmatrix phases.

// ============================================================================
// fp16-split tensor-core GEMM + BatchNorm epilogue.
// Y[z][o][n] = BN( (sum_c W[o][c]*X[z][c][n]) (+bias) )
// W scaled by 2^11 before split (keeps lo in fp16-normal range); accumulator
// descaled by exact 2^-11 in epilogue.
// NSPLIT=3 (3xFP16): Whi*Xhi + Wlo*Xhi + Whi*Xlo   (~2^-22 rel)
// NSPLIT=2 (binary B, exact-class): Whi*B + Wlo*B
// CTA 128x128, 8 warps of 64x32, K-chunk 16, double-buffered.
// ============================================================================
template<int NSPLIT>
__global__ __launch_bounds__(256, 2) void gemm_mma(
    const float* __restrict__ W, const float* __restrict__ X, float* __restrict__ Y,
    const float* __restrict__ gamma, const float* __restrict__ beta,
    const float* __restrict__ bias, float inv)
{
    __shared__ char smbuf[32768];
    // panels: Ah [2][4096] @0, Al @8192, Bh @16384, Bl @24576
    const uint32_t sbase = smem_u32(smbuf);

    const int tid  = threadIdx.x;
    const int lane = tid & 31;
    const int wid  = tid >> 5;
    const int wm   = (wid >> 2) * 64;   // warp m offset
    const int wn   = (wid & 3) * 32;    // warp n offset
    const int z  = blockIdx.z;
    const int m0 = blockIdx.y * 128;
    const int n0 = blockIdx.x * 128;

    const float* Xz = X + (size_t)z * CN;

    // loaders
    const int mA = tid & 127;
    const int jA = (tid >> 7) * 8;      // 0 or 8
    const int kB = tid >> 5;            // 0..7
    const int nB = (tid & 31) * 4;

    const float* Wrow = W + (size_t)(m0 + mA) * C_ + jA;
    const uint32_t abyte = (uint32_t)((mA * 2 + ((jA >> 3) ^ ((mA >> 2) & 1))) * 16);
    const uint32_t bbyte0 = (uint32_t)(kB * 256 + (((nB >> 3) ^ (kB & 7))) * 16 + (nB & 7) * 2);
    const int kB2 = kB + 8;
    const uint32_t bbyte1 = (uint32_t)(kB2 * 256 + (((nB >> 3) ^ (kB2 & 7))) * 16 + (nB & 7) * 2);

    // ldmatrix lane offsets
    const int mrel = (lane & 7) | (((lane >> 3) & 1) << 3);
    const int hA   = (lane >> 4) & 1;
    uint32_t offA[4];
#pragma unroll
    for (int mt = 0; mt < 4; mt++) {
        int m = wm + mt * 16 + mrel;
        offA[mt] = (uint32_t)((m * 2 + (hA ^ ((m >> 2) & 1))) * 16);
    }
    const int krel = (lane & 7) | (((lane >> 3) & 1) << 3);
    const int nrel = ((lane >> 4) & 1) * 8;
    uint32_t offB[2];
#pragma unroll
    for (int p = 0; p < 2; p++) {
        int n = wn + p * 16 + nrel;
        offB[p] = (uint32_t)(krel * 256 + (((n >> 3) ^ (krel & 7))) * 16);
    }

    float acc[4][4][4];
#pragma unroll
    for (int i = 0; i < 4; i++)
#pragma unroll
        for (int j = 0; j < 4; j++)
#pragma unroll
            for (int e = 0; e < 4; e++) acc[i][j][e] = 0.0f;

    float4 wa0, wa1, xb0, xb1;

    auto LDG = [&](int ch) {
        const int kb = ch * 16;
        wa0 = *(const float4*)(Wrow + kb);
        wa1 = *(const float4*)(Wrow + kb + 4);
        xb0 = *(const float4*)(Xz + (size_t)(kb + kB) * N_ + n0 + nB);
        xb1 = *(const float4*)(Xz + (size_t)(kb + 8 + kB) * N_ + n0 + nB);
    };

    auto STS = [&](int st) {
        char* Ah = smbuf + st * 4096;
        char* Al = smbuf + 8192 + st * 4096;
        char* Bh = smbuf + 16384 + st * 4096;
        char* Bl = smbuf + 24576 + st * 4096;
        // A: scale by 2^11, split hi/lo
        float wv[8] = {wa0.x, wa0.y, wa0.z, wa0.w, wa1.x, wa1.y, wa1.z, wa1.w};
        uint32_t ph[4], pl[4];
#pragma unroll
        for (int e = 0; e < 4; e++) {
            float s0 = wv[2 * e] * WSCALE, s1 = wv[2 * e + 1] * WSCALE;
            __half h0 = __float2half_rn(s0), h1 = __float2half_rn(s1);
            __half l0 = __float2half_rn(s0 - __half2float(h0));
            __half l1 = __float2half_rn(s1 - __half2float(h1));
            ph[e] = packh(h0, h1);
            pl[e] = packh(l0, l1);
        }
        *(uint4*)(Ah + abyte) = make_uint4(ph[0], ph[1], ph[2], ph[3]);
        *(uint4*)(Al + abyte) = make_uint4(pl[0], pl[1], pl[2], pl[3]);
        // B
        if (NSPLIT >= 3) {
            __half h0 = __float2half_rn(xb0.x), h1 = __float2half_rn(xb0.y);
            __half h2 = __float2half_rn(xb0.z), h3 = __float2half_rn(xb0.w);
            __half l0 = __float2half_rn(xb0.x - __half2float(h0));
            __half l1 = __float2half_rn(xb0.y - __half2float(h1));
            __half l2 = __float2half_rn(xb0.z - __half2float(h2));
            __half l3 = __float2half_rn(xb0.w - __half2float(h3));
            *(uint2*)(Bh + bbyte0) = make_uint2(packh(h0, h1), packh(h2, h3));
            *(uint2*)(Bl + bbyte0) = make_uint2(packh(l0, l1), packh(l2, l3));
            h0 = __float2half_rn(xb1.x); h1 = __float2half_rn(xb1.y);
            h2 = __float2half_rn(xb1.z); h3 = __float2half_rn(xb1.w);
            l0 = __float2half_rn(xb1.x - __half2float(h0));
            l1 = __float2half_rn(xb1.y - __half2float(h1));
            l2 = __float2half_rn(xb1.z - __half2float(h2));
            l3 = __float2half_rn(xb1.w - __half2float(h3));
            *(uint2*)(Bh + bbyte1) = make_uint2(packh(h0, h1), packh(h2, h3));
            *(uint2*)(Bl + bbyte1) = make_uint2(packh(l0, l1), packh(l2, l3));
        } else {
            // binary spikes: exact in fp16
            *(uint2*)(Bh + bbyte0) = make_uint2(
                packh(__float2half_rn(xb0.x), __float2half_rn(xb0.y)),
                packh(__float2half_rn(xb0.z), __float2half_rn(xb0.w)));
            *(uint2*)(Bh + bbyte1) = make_uint2(
                packh(__float2half_rn(xb1.x), __float2half_rn(xb1.y)),
                packh(__float2half_rn(xb1.z), __float2half_rn(xb1.w)));
        }
    };

    auto COMP = [&](int st) {
        const uint32_t aHi = sbase + st * 4096;
        const uint32_t aLo = sbase + 8192 + st * 4096;
        const uint32_t bHi = sbase + 16384 + st * 4096;
        const uint32_t bLo = sbase + 24576 + st * 4096;

        uint32_t ah[4][4], bh[4][2];
#pragma unroll
        for (int mt = 0; mt < 4; mt++) ldmx4(ah[mt], aHi + offA[mt]);
#pragma unroll
        for (int p = 0; p < 2; p++) {
            uint32_t t[4];
            ldmx4t(t, bHi + offB[p]);
            bh[2 * p][0] = t[0]; bh[2 * p][1] = t[1];
            bh[2 * p + 1][0] = t[2]; bh[2 * p + 1][1] = t[3];
        }
        // term 1: Whi x Bhi
#pragma unroll
        for (int mt = 0; mt < 4; mt++)
#pragma unroll
            for (int nt = 0; nt < 4; nt++) mma16(acc[mt][nt], ah[mt], bh[nt]);
        // term 3: Whi x Blo
        if (NSPLIT >= 3) {
            uint32_t bl[4][2];
#pragma unroll
            for (int p = 0; p < 2; p++) {
                uint32_t t[4];
                ldmx4t(t, bLo + offB[p]);
                bl[2 * p][0] = t[0]; bl[2 * p][1] = t[1];
                bl[2 * p + 1][0] = t[2]; bl[2 * p + 1][1] = t[3];
            }
#pragma unroll
            for (int mt = 0; mt < 4; mt++)
#pragma unroll
                for (int nt = 0; nt < 4; nt++) mma16(acc[mt][nt], ah[mt], bl[nt]);
        }
        // term 2: Wlo x Bhi (reuse ah registers)
#pragma unroll
        for (int mt = 0; mt < 4; mt++) ldmx4(ah[mt], aLo + offA[mt]);
#pragma unroll
        for (int mt = 0; mt < 4; mt++)
#pragma unroll
            for (int nt = 0; nt < 4; nt++) mma16(acc[mt][nt], ah[mt], bh[nt]);
    };

    LDG(0);
    STS(0);
    __syncthreads();
#pragma unroll 1
    for (int ch = 0; ch < 32; ch++) {
        if (ch < 31) LDG(ch + 1);
        COMP(ch & 1);
        if (ch < 31) STS((ch + 1) & 1);
        __syncthreads();
    }

    // Epilogue: descale (exact 2^-11), then BN in exact jax op order.
    {
        const int rb = m0 + wm + (lane >> 2);
        const int cb = n0 + wn + 2 * (lane & 3);
        float* Yz = Y + (size_t)z * CN;
#pragma unroll
        for (int mt = 0; mt < 4; mt++) {
            int r0 = rb + mt * 16, r1 = r0 + 8;
            float g0 = gamma[r0], g1 = gamma[r1];
            float e0 = beta[r0],  e1 = beta[r1];
            float b0 = bias ? bias[r0] : 0.0f;
            float b1 = bias ? bias[r1] : 0.0f;
#pragma unroll
            for (int nt = 0; nt < 4; nt++) {
                int cc = cb + nt * 8;
                float* c = acc[mt][nt];
                float v0 = __fmul_rn(c[0], WSCALE_INV);
                float v1 = __fmul_rn(c[1], WSCALE_INV);
                float v2 = __fmul_rn(c[2], WSCALE_INV);
                float v3 = __fmul_rn(c[3], WSCALE_INV);
                if (bias) { v0 = __fadd_rn(v0, b0); v1 = __fadd_rn(v1, b0);
                            v2 = __fadd_rn(v2, b1); v3 = __fadd_rn(v3, b1); }
                v0 = __fadd_rn(__fmul_rn(__fmul_rn(g0, v0), inv), e0);
                v1 = __fadd_rn(__fmul_rn(__fmul_rn(g0, v1), inv), e0);
                v2 = __fadd_rn(__fmul_rn(__fmul_rn(g1, v2), inv), e1);
                v3 = __fadd_rn(__fmul_rn(__fmul_rn(g1, v3), inv), e1);
                *(float2*)(Yz + (size_t)r0 * N_ + cc) = make_float2(v0, v1);
                *(float2*)(Yz + (size_t)r1 * N_ + cc) = make_float2(v2, v3);
            }
        }
    }
}

// ============================================================================
// Multi-step LIF: v' = v + (x - v)/2 ; s = (v' >= thr); hard reset.
// ============================================================================
__global__ void lif_kernel(const float* __restrict__ in, float* __restrict__ out, float thr)
{
    size_t idx = (size_t)blockIdx.x * blockDim.x + threadIdx.x;
    if (idx >= PER_T) return;
    float v = 0.0f;
#pragma unroll
    for (int t = 0; t < T_; t++) {
        float x = in[(size_t)t * PER_T + idx];
        v = __fadd_rn(v, __fmul_rn(__fsub_rn(x, v), 0.5f));
        float s = (v >= thr) ? 1.0f : 0.0f;
        if (v >= thr) v = 0.0f;
        out[(size_t)t * PER_T + idx] = s;
    }
}

// ============================================================================
// kv[t,b,h,d1,d2] = sum_n Sk[.,d1,n]*Sv[.,d2,n]   (integer-exact)
// ============================================================================
__global__ __launch_bounds__(256) void kv_kernel()
{
    int tbh = blockIdx.x;
    int tb = tbh >> 3, h = tbh & 7;
    const float* K = g_k + (size_t)tb * CN + (size_t)h * 64 * N_;
    const float* V = g_v + (size_t)tb * CN + (size_t)h * 64 * N_;

    __shared__ float Ks[64][65];
    __shared__ float Vs[64][65];

    const int tid = threadIdx.x;
    const int tx = tid & 15, ty = tid >> 4;
    const int r = tid >> 2;
    const int c0 = (tid & 3) * 4;

    float acc[4][4];
#pragma unroll
    for (int i = 0; i < 4; i++)
#pragma unroll
        for (int j = 0; j < 4; j++) acc[i][j] = 0.0f;

    for (int nc = 0; nc < 16; nc++) {
        int nbase = nc * 64;
        __syncthreads();
#pragma unroll
        for (int c4 = 0; c4 < 4; c4++) {
            int nn = c0 + c4 * 16;
            float4 k4 = *(const float4*)(K + (size_t)r * N_ + nbase + nn);
            float4 v4 = *(const float4*)(V + (size_t)r * N_ + nbase + nn);
            Ks[nn + 0][r] = k4.x; Ks[nn + 1][r] = k4.y;
            Ks[nn + 2][r] = k4.z; Ks[nn + 3][r] = k4.w;
            Vs[nn + 0][r] = v4.x; Vs[nn + 1][r] = v4.y;
            Vs[nn + 2][r] = v4.z; Vs[nn + 3][r] = v4.w;
        }
        __syncthreads();
#pragma unroll 8
        for (int nn = 0; nn < 64; nn++) {
            float a_[4], b_[4];
#pragma unroll
            for (int i = 0; i < 4; i++) a_[i] = Ks[nn][ty * 4 + i];
#pragma unroll
            for (int j = 0; j < 4; j++) b_[j] = Vs[nn][tx * 4 + j];
#pragma unroll
            for (int i = 0; i < 4; i++)
#pragma unroll
                for (int j = 0; j < 4; j++)
                    acc[i][j] += a_[i] * b_[j];
        }
    }

    float* kvb = g_kv + (size_t)tbh * 4096;
#pragma unroll
    for (int i = 0; i < 4; i++)
#pragma unroll
        for (int j = 0; j < 4; j++)
            kvb[(ty * 4 + i) * 64 + (tx * 4 + j)] = acc[i][j];
}

// ============================================================================
// a[t,b,h*64+e,n] = 0.125 * sum_d Sq[.,d,n] * kv[.,d,e]   (integer-exact)
// ============================================================================
__global__ __launch_bounds__(256) void av_kernel()
{
    int tbh = blockIdx.y;
    int tb = tbh >> 3, h = tbh & 7;
    int n0 = blockIdx.x * 128;
    const float* Q  = g_q  + (size_t)tb * CN + (size_t)h * 64 * N_;
    const float* KV = g_kv + (size_t)tbh * 4096;
    float*       A  = g_a  + (size_t)tb * CN + (size_t)h * 64 * N_;

    __shared__ float Qs[64][128];
    __shared__ float KVs[64][64];

    const int tid = threadIdx.x;
#pragma unroll
    for (int i = 0; i < 4; i++) {
        int idx = tid + i * 256;
        int r = idx >> 4, c = (idx & 15) * 4;
        *(float4*)&KVs[r][c] = *(const float4*)(KV + (size_t)r * 64 + c);
    }
#pragma unroll
    for (int i = 0; i < 8; i++) {
        int idx = tid + i * 256;
        int r = idx >> 5, c = (idx & 31) * 4;
        *(float4*)&Qs[r][c] = *(const float4*)(Q + (size_t)r * N_ + n0 + c);
    }
    __syncthreads();

    const int tx = tid & 31, ty = tid >> 5;
    float acc[8][4];
#pragma unroll
    for (int i = 0; i < 8; i++)
#pragma unroll
        for (int j = 0; j < 4; j++) acc[i][j] = 0.0f;

#pragma unroll 8
    for (int d = 0; d < 64; d++) {
        float4 q4 = *(const float4*)&Qs[d][tx * 4];
#pragma unroll
        for (int i = 0; i < 8; i++) {
            float kvv = KVs[d][ty * 8 + i];
            acc[i][0] += kvv * q4.x;
            acc[i][1] += kvv * q4.y;
            acc[i][2] += kvv * q4.z;
            acc[i][3] += kvv * q4.w;
        }
    }

#pragma unroll
    for (int i = 0; i < 8; i++) {
        int e = ty * 8 + i;
#pragma unroll
        for (int j = 0; j < 4; j++)
            A[(size_t)e * N_ + n0 + tx * 4 + j] = acc[i][j] * 0.125f;
    }
}

// ============================================================================
extern "C" void kernel_launch(void* const* d_in, const int* in_sizes, int n_in,
                              void* d_out, int out_size)
{
    const float* x   = (const float*)d_in[0];
    const float* Wq  = (const float*)d_in[1];
    const float* qg  = (const float*)d_in[2];
    const float* qb  = (const float*)d_in[3];
    const float* Wk  = (const float*)d_in[4];
    const float* kg  = (const float*)d_in[5];
    const float* kb  = (const float*)d_in[6];
    const float* Wv  = (const float*)d_in[7];
    const float* vg  = (const float*)d_in[8];
    const float* vb  = (const float*)d_in[9];
    const float* Wp  = (const float*)d_in[10];
    const float* bp  = (const float*)d_in[11];
    const float* pg  = (const float*)d_in[12];
    const float* pb  = (const float*)d_in[13];
    float* out = (float*)d_out;

    float *q, *k, *v, *a, *p;
    cudaGetSymbolAddress((void**)&q, g_q);
    cudaGetSymbolAddress((void**)&k, g_k);
    cudaGetSymbolAddress((void**)&v, g_v);
    cudaGetSymbolAddress((void**)&a, g_a);
    cudaGetSymbolAddress((void**)&p, g_p);

    float one_eps = 1.0f + 1e-5f;
    float inv = (float)(1.0 / sqrt((double)one_eps));

    dim3 gg(N_ / 128, C_ / 128, TB);   // 8 x 4 x 32

    gemm_mma<3><<<gg, 256>>>(Wq, x, q, qg, qb, nullptr, inv);
    gemm_mma<3><<<gg, 256>>>(Wk, x, k, kg, kb, nullptr, inv);
    gemm_mma<3><<<gg, 256>>>(Wv, x, v, vg, vb, nullptr, inv);

    lif_kernel<<<PER_T / 256, 256>>>(q, q, 1.0f);
    lif_kernel<<<PER_T / 256, 256>>>(k, k, 1.0f);
    lif_kernel<<<PER_T / 256, 256>>>(v, v, 1.0f);

    kv_kernel<<<256, 256>>>();
    av_kernel<<<dim3(N_ / 128, 256), 256>>>();

    lif_kernel<<<PER_T / 256, 256>>>(a, a, 0.5f);

    gemm_mma<2><<<gg, 256>>>(Wp, a, p, pg, pb, bp, inv);

    lif_kernel<<<PER_T / 256, 256>>>(p, out, 1.0f);
}